// round 17
// baseline (speedup 1.0000x reference)
#include <cuda_runtime.h>
#include <cuda_bf16.h>
#include <stdint.h>

#define N_NODES  50000
#define N_EDGES  800000
#define F        128
#define N_GRAPHS 128
#define N_CLASSES 10

#define NCHUNK   4
#define CH_BLK   196                  // gemm blocks per chunk (64 rows each)
#define CH_ROWS  (CH_BLK * 64)        // 12544 rows per chunk

// ---------------- scratch (no allocations allowed) ----------------
__device__ __align__(16) float g_HA[N_NODES * F];    // H ping
__device__ __align__(16) float g_HB[N_NODES * F];    // H pong
__device__ __align__(16) float g_ACC[N_NODES * F];   // aggregated layer output
__device__ float g_dinv[N_NODES];
__device__ int   g_degi[N_NODES];
__device__ int   g_rowbeg[N_NODES];
__device__ int   g_cursor[N_NODES];
__device__ int   g_alloc;
__device__ int   g_csrc[N_EDGES];
__device__ float g_cnorm[N_EDGES];
__device__ __align__(16) float g_gsum[N_GRAPHS * F];

__device__ __forceinline__ void red_add_v4(float* p, float4 v) {
    asm volatile("red.relaxed.gpu.global.add.v4.f32 [%0], {%1, %2, %3, %4};"
                 :: "l"(p), "f"(v.x), "f"(v.y), "f"(v.z), "f"(v.w)
                 : "memory");
}

// ---------------- packed f32x2 helpers (Blackwell FFMA2) ----------------
__device__ __forceinline__ unsigned long long pack2(float lo, float hi) {
    unsigned long long r;
    asm("mov.b64 %0, {%1, %2};" : "=l"(r) : "f"(lo), "f"(hi));
    return r;
}
__device__ __forceinline__ void fma2(unsigned long long& d,
                                     unsigned long long a, unsigned long long b) {
    asm("fma.rn.f32x2 %0, %1, %2, %0;" : "+l"(d) : "l"(a), "l"(b));
}
__device__ __forceinline__ float2 unpack2(unsigned long long v) {
    float2 r;
    asm("mov.b64 {%0, %1}, %2;" : "=f"(r.x), "=f"(r.y) : "l"(v));
    return r;
}

// ---------------- precompute ----------------
__global__ void k_init() {
    int i = blockIdx.x * blockDim.x + threadIdx.x;
    if (i < N_NODES) g_degi[i] = 0;
    if (i < N_GRAPHS * F) g_gsum[i] = 0.0f;
    if (i == 0) g_alloc = 0;
}

__global__ void k_deg(const int* __restrict__ ei) {
    int e = blockIdx.x * blockDim.x + threadIdx.x;
    if (e < N_EDGES) atomicAdd(&g_degi[ei[N_EDGES + e]], 1);
}

// warp-aggregated segment allocation: one global atomic per warp
__global__ void k_alloc_seg() {
    int i    = blockIdx.x * blockDim.x + threadIdx.x;
    int lane = threadIdx.x & 31;
    int deg  = (i < N_NODES) ? g_degi[i] : 0;
    int scan = deg;
    #pragma unroll
    for (int o = 1; o < 32; o <<= 1) {
        int t = __shfl_up_sync(0xFFFFFFFFu, scan, o);
        if (lane >= o) scan += t;
    }
    int total = __shfl_sync(0xFFFFFFFFu, scan, 31);
    int base = 0;
    if (lane == 31) base = atomicAdd(&g_alloc, total);
    base = __shfl_sync(0xFFFFFFFFu, base, 31);
    if (i < N_NODES) {
        int pos = base + scan - deg;
        g_rowbeg[i] = pos;
        g_cursor[i] = pos;
        g_dinv[i]   = rsqrtf((float)deg + 1.0f);
    }
}

__global__ void k_fill(const int* __restrict__ ei) {
    int e = blockIdx.x * blockDim.x + threadIdx.x;
    if (e < N_EDGES) {
        int s = ei[e];
        int d = ei[N_EDGES + e];
        int pos = atomicAdd(&g_cursor[d], 1);
        g_csrc[pos]  = s;
        g_cnorm[pos] = g_dinv[s] * g_dinv[d];
    }
}

// ---------------- GEMM: H = act(X) @ W  (FFMA2, zipped row-pair X) ----------
// MODE 0: read Xin (no relu). MODE 1: read relu(g_ACC).
// DST 0: write g_HA. DST 1: write g_HB.
// row_base: starting row of this chunk (chunk-local grid).
template <int MODE, int DST>
__global__ void __launch_bounds__(256, 2)
k_gemm(const float* __restrict__ Xin, const float* __restrict__ W, int row_base) {
    extern __shared__ float smem[];
    float* sW  = smem;            // [128][128] = 64 KB
    float* sXz = smem + F * F;    // [32 rp][128 k][2] = 32 KB

    float* __restrict__ Hout = (DST == 0) ? g_HA : g_HB;

    const int tid  = threadIdx.x;
    const int row0 = row_base + blockIdx.x * 64;

    #pragma unroll
    for (int i = 0; i < 16; i++)
        ((float4*)sW)[tid + i * 256] = ((const float4*)W)[tid + i * 256];

    const float* src = (MODE == 0) ? Xin : g_ACC;
    #pragma unroll
    for (int i = 0; i < 4; i++) {
        int idx = tid + i * 256;          // over 32 k4-groups x 32 row-pairs
        int k4  = idx & 31;
        int rp  = idx >> 5;
        int r0  = row0 + 2 * rp;
        float4 a = make_float4(0.f, 0.f, 0.f, 0.f);
        float4 b = make_float4(0.f, 0.f, 0.f, 0.f);
        if (r0 < N_NODES)     a = ((const float4*)(src + (size_t)r0 * F))[k4];
        if (r0 + 1 < N_NODES) b = ((const float4*)(src + (size_t)(r0 + 1) * F))[k4];
        if (MODE == 1) {
            a.x = fmaxf(a.x, 0.f); a.y = fmaxf(a.y, 0.f);
            a.z = fmaxf(a.z, 0.f); a.w = fmaxf(a.w, 0.f);
            b.x = fmaxf(b.x, 0.f); b.y = fmaxf(b.y, 0.f);
            b.z = fmaxf(b.z, 0.f); b.w = fmaxf(b.w, 0.f);
        }
        float2* dst = (float2*)&sXz[rp * 256 + k4 * 8];
        dst[0] = make_float2(a.x, b.x);
        dst[1] = make_float2(a.y, b.y);
        dst[2] = make_float2(a.z, b.z);
        dst[3] = make_float2(a.w, b.w);
    }
    __syncthreads();

    const int wp = tid >> 5;     // warp 0..7 -> row-pairs 4wp..4wp+3
    const int cg = tid & 31;     // lane -> cols 4cg..4cg+3

    unsigned long long acc[4][4];   // [row-pair][col], pair over rows
    #pragma unroll
    for (int i = 0; i < 4; i++)
        #pragma unroll
        for (int j = 0; j < 4; j++) acc[i][j] = 0ull;

    #pragma unroll 4
    for (int k = 0; k < F; k += 2) {
        float4 wa = *(float4*)&sW[k * F + cg * 4];
        float4 wb = *(float4*)&sW[(k + 1) * F + cg * 4];
        unsigned long long wa0 = pack2(wa.x, wa.x), wa1 = pack2(wa.y, wa.y);
        unsigned long long wa2 = pack2(wa.z, wa.z), wa3 = pack2(wa.w, wa.w);
        unsigned long long wb0 = pack2(wb.x, wb.x), wb1 = pack2(wb.y, wb.y);
        unsigned long long wb2 = pack2(wb.z, wb.z), wb3 = pack2(wb.w, wb.w);
        #pragma unroll
        for (int rp = 0; rp < 4; rp++) {
            ulonglong2 xp = *(const ulonglong2*)&sXz[(4 * wp + rp) * 256 + k * 2];
            fma2(acc[rp][0], xp.x, wa0); fma2(acc[rp][1], xp.x, wa1);
            fma2(acc[rp][2], xp.x, wa2); fma2(acc[rp][3], xp.x, wa3);
            fma2(acc[rp][0], xp.y, wb0); fma2(acc[rp][1], xp.y, wb1);
            fma2(acc[rp][2], xp.y, wb2); fma2(acc[rp][3], xp.y, wb3);
        }
    }

    #pragma unroll
    for (int rp = 0; rp < 4; rp++) {
        int r = row0 + 2 * (4 * wp + rp);
        float2 p0 = unpack2(acc[rp][0]);
        float2 p1 = unpack2(acc[rp][1]);
        float2 p2 = unpack2(acc[rp][2]);
        float2 p3 = unpack2(acc[rp][3]);
        if (r < N_NODES)
            *(float4*)&Hout[(size_t)r * F + cg * 4] =
                make_float4(p0.x, p1.x, p2.x, p3.x);
        if (r + 1 < N_NODES)
            *(float4*)&Hout[(size_t)(r + 1) * F + cg * 4] =
                make_float4(p0.y, p1.y, p2.y, p3.y);
    }
}

// ---------------- aggregate: ACC[d] = sum_in norm*H[s] + dinv[d]^2*H[d] + b ----
// SRC 0: read g_HA. SRC 1: read g_HB.
// POOL=1: RED the result into g_gsum[batch[d]] instead of storing ACC.
// node_base/node_cnt: chunk of destination nodes.
template <int POOL, int SRC>
__global__ void __launch_bounds__(256)
k_aggregate(const float* __restrict__ bias, const int* __restrict__ batch,
            int node_base, int node_cnt) {
    const int warp = (blockIdx.x * blockDim.x + threadIdx.x) >> 5;
    const int lane = threadIdx.x & 31;
    if (warp >= node_cnt) return;
    const int d = node_base + warp;

    const float* __restrict__ Hsrc = (SRC == 0) ? g_HA : g_HB;

    const int beg = __ldg(&g_rowbeg[d]);
    const int end = beg + __ldg(&g_degi[d]);
    const float di = __ldg(&g_dinv[d]);

    float4 acc = *(const float4*)&Hsrc[(size_t)d * F + lane * 4];
    float sn = di * di;
    acc.x *= sn; acc.y *= sn; acc.z *= sn; acc.w *= sn;

    int j = beg;
    if (j < end) {
        int   s0 = __ldg(&g_csrc[j]);
        float n0 = __ldg(&g_cnorm[j]);
        float4 v0 = *(const float4*)&Hsrc[(size_t)s0 * F + lane * 4];
        for (j = beg + 1; j < end; j++) {
            int   s1 = __ldg(&g_csrc[j]);
            float n1 = __ldg(&g_cnorm[j]);
            float4 v1 = *(const float4*)&Hsrc[(size_t)s1 * F + lane * 4];
            acc.x += n0 * v0.x; acc.y += n0 * v0.y;
            acc.z += n0 * v0.z; acc.w += n0 * v0.w;
            v0 = v1; n0 = n1;
        }
        acc.x += n0 * v0.x; acc.y += n0 * v0.y;
        acc.z += n0 * v0.z; acc.w += n0 * v0.w;
    }

    float4 bv = *(const float4*)&bias[lane * 4];
    acc.x += bv.x; acc.y += bv.y; acc.z += bv.z; acc.w += bv.w;

    if (POOL) {
        int g = __ldg(&batch[d]);
        red_add_v4(&g_gsum[g * F + lane * 4], acc);
    } else {
        *(float4*)&g_ACC[(size_t)d * F + lane * 4] = acc;
    }
}

// ---------------- head: counts from sorted batch_ids via binary search ------
__global__ void k_final(const int* __restrict__ batch,
                        const float* __restrict__ lin_w,
                        const float* __restrict__ lin_b,
                        float* __restrict__ out) {
    int g = blockIdx.x;
    int c = threadIdx.x;
    __shared__ float s_cnt;
    if (c == 0) {
        int lo = 0, hi = N_NODES;               // lower_bound(g)
        while (lo < hi) { int m = (lo + hi) >> 1; if (__ldg(&batch[m]) < g) lo = m + 1; else hi = m; }
        int lo2 = lo, hi2 = N_NODES;            // upper_bound(g)
        while (lo2 < hi2) { int m = (lo2 + hi2) >> 1; if (__ldg(&batch[m]) <= g) lo2 = m + 1; else hi2 = m; }
        s_cnt = (float)(lo2 - lo);
    }
    __syncthreads();
    if (c >= N_CLASSES) return;
    float cnt = fmaxf(s_cnt, 1.0f);
    float acc = 0.f;
    #pragma unroll 8
    for (int f = 0; f < F; f++)
        acc += g_gsum[g * F + f] * __ldg(&lin_w[f * N_CLASSES + c]);
    out[g * N_CLASSES + c] = acc / cnt + lin_b[c];
}

// ---------------- host ----------------
extern "C" void kernel_launch(void* const* d_in, const int* in_sizes, int n_in,
                              void* d_out, int out_size) {
    const float* x     = (const float*)d_in[0];
    const int*   ei    = (const int*)d_in[1];
    const int*   batch = (const int*)d_in[2];
    const float* w1 = (const float*)d_in[3];
    const float* b1 = (const float*)d_in[4];
    const float* w2 = (const float*)d_in[5];
    const float* b2 = (const float*)d_in[6];
    const float* w3 = (const float*)d_in[7];
    const float* b3 = (const float*)d_in[8];
    const float* lw = (const float*)d_in[9];
    const float* lb = (const float*)d_in[10];
    float* out = (float*)d_out;

    static bool         s_ready = false;
    static cudaStream_t s_side;
    static cudaEvent_t  s_fork, s_join, eA[NCHUNK], eB[NCHUNK], eG2, eG3;
    if (!s_ready) {
        cudaStreamCreateWithFlags(&s_side, cudaStreamNonBlocking);
        cudaEventCreateWithFlags(&s_fork, cudaEventDisableTiming);
        cudaEventCreateWithFlags(&s_join, cudaEventDisableTiming);
        for (int c = 0; c < NCHUNK; c++) {
            cudaEventCreateWithFlags(&eA[c], cudaEventDisableTiming);
            cudaEventCreateWithFlags(&eB[c], cudaEventDisableTiming);
        }
        cudaEventCreateWithFlags(&eG2, cudaEventDisableTiming);
        cudaEventCreateWithFlags(&eG3, cudaEventDisableTiming);
        s_ready = true;
    }

    const int SMEM = (F * F + 64 * F) * (int)sizeof(float);   // 96 KB
    cudaFuncSetAttribute((const void*)k_gemm<0,0>, cudaFuncAttributeMaxDynamicSharedMemorySize, SMEM);
    cudaFuncSetAttribute((const void*)k_gemm<1,1>, cudaFuncAttributeMaxDynamicSharedMemorySize, SMEM);
    cudaFuncSetAttribute((const void*)k_gemm<1,0>, cudaFuncAttributeMaxDynamicSharedMemorySize, SMEM);

    const int GB = (N_NODES + 63) / 64;      // 782
    const int EB = (N_EDGES + 255) / 256;
    const int NB = (N_NODES + 255) / 256;

    // fork: CSR build on side stream, concurrent with layer-1 GEMM
    cudaEventRecord(s_fork, 0);
    cudaStreamWaitEvent(s_side, s_fork, 0);
    k_init<<<NB, 256, 0, s_side>>>();
    k_deg<<<EB, 256, 0, s_side>>>(ei);
    k_alloc_seg<<<NB, 256, 0, s_side>>>();
    k_fill<<<EB, 256, 0, s_side>>>(ei);
    cudaEventRecord(s_join, s_side);

    k_gemm<0,0><<<GB, 256, SMEM>>>(x, w1, 0);      // layer-1 GEMM -> HA

    cudaStreamWaitEvent(0, s_join, 0);             // CSR ready before aggregates

    // ---- boundary 1: agg1 (HA->ACC) chunks overlap gemm2 (ACC->HB) chunks ----
    for (int c = 0; c < NCHUNK; c++) {
        int base = c * CH_ROWS;
        int cnt  = (base + CH_ROWS <= N_NODES) ? CH_ROWS : (N_NODES - base);
        int blocks = (cnt + 7) / 8;
        k_aggregate<0,0><<<blocks, 256>>>(b1, batch, base, cnt);
        cudaEventRecord(eA[c], 0);
        cudaStreamWaitEvent(s_side, eA[c], 0);
        int gblocks = (cnt + 63) / 64;
        k_gemm<1,1><<<gblocks, 256, SMEM, s_side>>>(x, w2, base);
    }
    cudaEventRecord(eG2, s_side);
    cudaStreamWaitEvent(0, eG2, 0);                // full HB before agg2

    // ---- boundary 2: agg2 (HB->ACC) chunks overlap gemm3 (ACC->HA) chunks ----
    for (int c = 0; c < NCHUNK; c++) {
        int base = c * CH_ROWS;
        int cnt  = (base + CH_ROWS <= N_NODES) ? CH_ROWS : (N_NODES - base);
        int blocks = (cnt + 7) / 8;
        k_aggregate<0,1><<<blocks, 256>>>(b2, batch, base, cnt);
        cudaEventRecord(eB[c], 0);
        cudaStreamWaitEvent(s_side, eB[c], 0);
        int gblocks = (cnt + 63) / 64;
        k_gemm<1,0><<<gblocks, 256, SMEM, s_side>>>(x, w3, base);
    }
    cudaEventRecord(eG3, s_side);
    cudaStreamWaitEvent(0, eG3, 0);                // full HA before agg3

    // ---- final aggregate + fused mean-pool, then head ----
    k_aggregate<1,0><<<(N_NODES + 7) / 8, 256>>>(b3, batch, 0, N_NODES);
    k_final<<<N_GRAPHS, 32>>>(batch, lw, lb, out);
}